// round 1
// baseline (speedup 1.0000x reference)
#include <cuda_runtime.h>

#define INPUT_DIM 256
#define QN        12
#define NCTRL     25
#define NSPANS    22   // NCTRL - DEGREE

// ---------- f32x2 packed helpers (ptxas never auto-fuses; PTX only) ----------
__device__ __forceinline__ unsigned long long pack2(float a, float b) {
    unsigned long long r;
    asm("mov.b64 %0, {%1, %2};" : "=l"(r) : "f"(a), "f"(b));
    return r;
}
__device__ __forceinline__ void fma2(unsigned long long& d, unsigned long long a,
                                     unsigned long long b) {
    asm("fma.rn.f32x2 %0, %1, %2, %3;" : "=l"(d) : "l"(a), "l"(b), "l"(d));
}
__device__ __forceinline__ void unpack2(unsigned long long v, float& x, float& y) {
    asm("mov.b64 {%0, %1}, %2;" : "=f"(x), "=f"(y) : "l"(v));
}

// Open-uniform knot value: knots[i] = clamp(i-3, 0, 22) / 22
__device__ __forceinline__ float knot_at(int i) {
    int c = i - 3;
    c = c < 0 ? 0 : (c > NSPANS ? NSPANS : c);
    return (float)c * (1.0f / (float)NSPANS);
}

__global__ __launch_bounds__(128, 3)
void ka_bspline_kernel(const float* __restrict__ emb,
                       const float* __restrict__ W,
                       const float* __restrict__ b_inner,
                       const float* __restrict__ inner_scale,
                       const float* __restrict__ coeffs,
                       const float* __restrict__ a_out,
                       const float* __restrict__ b_out,
                       float* __restrict__ out,
                       int npts)
{
    __shared__ float csh[QN * NCTRL];
    for (int k = threadIdx.x; k < QN * NCTRL; k += blockDim.x) csh[k] = coeffs[k];
    __syncthreads();

    const int lane  = threadIdx.x & 31;
    const int h     = lane >> 4;      // half-warp id: 0 -> q 0..5, 1 -> q 6..11
    const int t     = lane & 15;      // sublane within half
    const int qbase = 6 * h;

    // W resident in registers: this lane covers dims {4*(t+16i)+d} for its 6 q's,
    // packed as f32x2 over adjacent q pairs. 48 x 64-bit regs.
    unsigned long long wreg[48];
#pragma unroll
    for (int i = 0; i < 4; i++) {
#pragma unroll
        for (int d = 0; d < 4; d++) {
            const int D = 4 * (t + 16 * i) + d;
#pragma unroll
            for (int p = 0; p < 3; p++) {
                float w0 = W[(qbase + 2 * p)     * INPUT_DIM + D];
                float w1 = W[(qbase + 2 * p + 1) * INPUT_DIM + D];
                wreg[(i * 4 + d) * 3 + p] = pack2(w0, w1);
            }
        }
    }

    const float sc2 = -2.0f * inner_scale[0];   // s = 1/(1+exp(sc2*u)) == 0.5*(tanh(scale*u)+1)
    const float bo  = b_out[0];
    const int   qe  = qbase + (t < 6 ? t : 0);
    const float my_bi = b_inner[qe];
    const float my_a  = a_out[qe];
    const float* __restrict__ crow = csh + qe * NCTRL;

    const int  wpb    = blockDim.x >> 5;
    const long twarps = (long)gridDim.x * wpb;
    long n = (long)blockIdx.x * wpb + (threadIdx.x >> 5);

    const float4* __restrict__ emb4 = (const float4*)emb;

    float4 e0, e1, e2, e3;
    if (n < npts) {
        const float4* b = emb4 + (size_t)n * 64 + t;
        e0 = b[0]; e1 = b[16]; e2 = b[32]; e3 = b[48];
    }

    while (n < npts) {
        const long n2 = n + twarps;
        float4 f0 = {0,0,0,0}, f1 = {0,0,0,0}, f2 = {0,0,0,0}, f3 = {0,0,0,0};
        if (n2 < npts) {  // prefetch next point while we compute
            const float4* b = emb4 + (size_t)n2 * 64 + t;
            f0 = b[0]; f1 = b[16]; f2 = b[32]; f3 = b[48];
        }

        unsigned long long acc0 = 0ull, acc1 = 0ull, acc2 = 0ull;
#define KA_DO1(EV, IDX)                                                    \
        {                                                                  \
            unsigned long long ex = pack2((EV), (EV));                     \
            fma2(acc0, ex, wreg[(IDX) * 3 + 0]);                           \
            fma2(acc1, ex, wreg[(IDX) * 3 + 1]);                           \
            fma2(acc2, ex, wreg[(IDX) * 3 + 2]);                           \
        }
#define KA_DO4(E, I)                                                       \
        KA_DO1((E).x, (I)*4 + 0) KA_DO1((E).y, (I)*4 + 1)                  \
        KA_DO1((E).z, (I)*4 + 2) KA_DO1((E).w, (I)*4 + 3)

        KA_DO4(e0, 0) KA_DO4(e1, 1) KA_DO4(e2, 2) KA_DO4(e3, 3)
#undef KA_DO4
#undef KA_DO1

        float r0, r1, r2, r3, r4, r5;
        unpack2(acc0, r0, r1);
        unpack2(acc1, r2, r3);
        unpack2(acc2, r4, r5);

        // butterfly reduce within each 16-lane half (xor offsets stay inside the half)
#pragma unroll
        for (int off = 8; off; off >>= 1) {
            r0 += __shfl_xor_sync(0xffffffffu, r0, off);
            r1 += __shfl_xor_sync(0xffffffffu, r1, off);
            r2 += __shfl_xor_sync(0xffffffffu, r2, off);
            r3 += __shfl_xor_sync(0xffffffffu, r3, off);
            r4 += __shfl_xor_sync(0xffffffffu, r4, off);
            r5 += __shfl_xor_sync(0xffffffffu, r5, off);
        }

        float v = 0.0f;
        if (t < 6) {
            float rv = (t == 0) ? r0 : (t == 1) ? r1 : (t == 2) ? r2
                     : (t == 3) ? r3 : (t == 4) ? r4 : r5;
            const float u = rv + my_bi;
            float s = 1.0f / (1.0f + __expf(sc2 * u));   // == 0.5*(tanh+1), clamped to (0,1]

            // span index: knots[j] <= s < knots[j+1], j in [3, 24]
            int sp = (int)(s * (float)NSPANS);
            sp = sp > (NSPANS - 1) ? (NSPANS - 1) : (sp < 0 ? 0 : sp);
            const int j = sp + 3;

            const float l1  = s - knot_at(j);
            const float rr1 = knot_at(j + 1) - s;
            const float l2  = s - knot_at(j - 1);
            const float rr2 = knot_at(j + 2) - s;
            const float l3  = s - knot_at(j - 2);
            const float rr3 = knot_at(j + 3) - s;

            // local de Boor (only the 4 nonzero cubic basis functions)
            float N0, N1, N2, N3, tp, sv;
            tp = __fdividef(1.0f, rr1 + l1);  N0 = rr1 * tp;  N1 = l1 * tp;
            // p = 2
            tp = __fdividef(N0, rr1 + l2);    N0 = rr1 * tp;  sv = l2 * tp;
            tp = __fdividef(N1, rr2 + l1);    N1 = sv + rr2 * tp;  N2 = l1 * tp;
            // p = 3
            tp = __fdividef(N0, rr1 + l3);    N0 = rr1 * tp;  sv = l3 * tp;
            tp = __fdividef(N1, rr2 + l2);    N1 = sv + rr2 * tp;  sv = l2 * tp;
            tp = __fdividef(N2, rr3 + l1);    N2 = sv + rr3 * tp;  N3 = l1 * tp;

            const float phi = N0 * crow[j - 3] + N1 * crow[j - 2]
                            + N2 * crow[j - 1] + N3 * crow[j];
            v = phi * my_a;
        }

        // sum the 12 per-q contributions across the full warp
#pragma unroll
        for (int off = 16; off; off >>= 1)
            v += __shfl_xor_sync(0xffffffffu, v, off);

        if (lane == 0) out[n] = v + bo;

        e0 = f0; e1 = f1; e2 = f2; e3 = f3;
        n = n2;
    }
}

extern "C" void kernel_launch(void* const* d_in, const int* in_sizes, int n_in,
                              void* d_out, int out_size)
{
    const float* emb         = (const float*)d_in[0];
    const float* W           = (const float*)d_in[1];
    const float* b_inner     = (const float*)d_in[2];
    const float* inner_scale = (const float*)d_in[3];
    const float* coeffs      = (const float*)d_in[4];
    const float* a_out       = (const float*)d_in[5];
    const float* b_out       = (const float*)d_in[6];
    float* out = (float*)d_out;

    const int npts = in_sizes[0] / INPUT_DIM;

    // persistent-style grid: 3 blocks/SM * ~152 SMs
    ka_bspline_kernel<<<456, 128>>>(emb, W, b_inner, inner_scale, coeffs,
                                    a_out, b_out, out, npts);
}

// round 8
// speedup vs baseline: 1.5324x; 1.5324x over previous
#include <cuda_runtime.h>

#define INPUT_DIM 256
#define QN        12
#define NCTRL     25
#define NSPANS    22   // NCTRL - DEGREE

// ---------- f32x2 packed helpers (ptxas never auto-fuses; PTX only) ----------
__device__ __forceinline__ unsigned long long pack2(float a, float b) {
    unsigned long long r;
    asm("mov.b64 %0, {%1, %2};" : "=l"(r) : "f"(a), "f"(b));
    return r;
}
__device__ __forceinline__ void fma2(unsigned long long& d, unsigned long long a,
                                     unsigned long long b) {
    asm("fma.rn.f32x2 %0, %1, %2, %3;" : "=l"(d) : "l"(a), "l"(b), "l"(d));
}
__device__ __forceinline__ void unpack2(unsigned long long v, float& x, float& y) {
    asm("mov.b64 {%0, %1}, %2;" : "=f"(x), "=f"(y) : "l"(v));
}

__global__ __launch_bounds__(128, 3)
void ka_bspline_kernel(const float* __restrict__ emb,
                       const float* __restrict__ W,
                       const float* __restrict__ b_inner,
                       const float* __restrict__ inner_scale,
                       const float* __restrict__ coeffs,
                       const float* __restrict__ a_out,
                       const float* __restrict__ b_out,
                       float* __restrict__ out,
                       int npts)
{
    __shared__ float csh[QN * NCTRL];
    for (int k = threadIdx.x; k < QN * NCTRL; k += blockDim.x) csh[k] = coeffs[k];
    __syncthreads();

    const int  lane = threadIdx.x & 31;
    const bool hi16 = (lane & 16) != 0;
    const bool b3 = (lane & 8) != 0;
    const bool b2 = (lane & 4) != 0;
    const bool b1 = (lane & 2) != 0;
    const bool b0 = (lane & 1) != 0;

    // W resident in registers. Lane l owns dims {4l..4l+3, 128+4l..128+4l+3},
    // packed f32x2 over adjacent dims so emb float4 halves are natural operands.
    unsigned long long wreg[QN * 4];
#pragma unroll
    for (int q = 0; q < QN; q++) {
        const int D0 = 4 * lane;
        const int D1 = 128 + 4 * lane;
        const float* wr = W + q * INPUT_DIM;
        wreg[q * 4 + 0] = pack2(wr[D0],     wr[D0 + 1]);
        wreg[q * 4 + 1] = pack2(wr[D0 + 2], wr[D0 + 3]);
        wreg[q * 4 + 2] = pack2(wr[D1],     wr[D1 + 1]);
        wreg[q * 4 + 3] = pack2(wr[D1 + 2], wr[D1 + 3]);
    }

    // After reduce-scatter, lane l holds u for q = l & 15 (point A on lanes 0..15,
    // point B on lanes 16..31). Lanes with q >= 12 are dead.
    const int  q15    = lane & 15;
    const bool active = (q15 < QN);
    const int  qc     = active ? q15 : 0;
    const float my_bi = b_inner[qc];
    const float my_a  = a_out[qc];
    const float* __restrict__ crow = csh + qc * NCTRL;

    const float sc2 = -2.0f * inner_scale[0];  // s = 1/(1+exp(sc2*u))
    const float bo  = b_out[0];

    const int  wpb    = blockDim.x >> 5;
    const long T      = (long)gridDim.x * wpb;
    const long stride = 2 * T;
    long n = (long)blockIdx.x * wpb + (threadIdx.x >> 5);

    const float4* __restrict__ emb4 = (const float4*)emb;
    const float4 z4 = {0.f, 0.f, 0.f, 0.f};

    // Role swap: lanes 16..31 treat point B as "Lo" -> round-1 of the
    // reduce-scatter needs no selects at all.
    float4 eL0 = z4, eL1 = z4, eH0 = z4, eH1 = z4;
    {
        const long nA = n, nB = n + T;
        const long nLo = hi16 ? nB : nA;
        const long nHi = hi16 ? nA : nB;
        if (nLo < npts) { const float4* p = emb4 + (size_t)nLo * 64 + lane; eL0 = p[0]; eL1 = p[32]; }
        if (nHi < npts) { const float4* p = emb4 + (size_t)nHi * 64 + lane; eH0 = p[0]; eH1 = p[32]; }
    }

    while (n < npts) {
        const long nA = n, nB = n + T, nn = n + stride;

        // prefetch next pair (role-swapped)
        float4 fL0 = z4, fL1 = z4, fH0 = z4, fH1 = z4;
        {
            const long mA = nn, mB = nn + T;
            const long mLo = hi16 ? mB : mA;
            const long mHi = hi16 ? mA : mB;
            if (mLo < npts) { const float4* p = emb4 + (size_t)mLo * 64 + lane; fL0 = p[0]; fL1 = p[32]; }
            if (mHi < npts) { const float4* p = emb4 + (size_t)mHi * 64 + lane; fH0 = p[0]; fH1 = p[32]; }
        }

        // ---- GEMM partials: Lo point then Hi point (acc regs reused) ----
        float rL[QN], rH[QN];
        {
            const unsigned long long p0 = pack2(eL0.x, eL0.y);
            const unsigned long long p1 = pack2(eL0.z, eL0.w);
            const unsigned long long p2 = pack2(eL1.x, eL1.y);
            const unsigned long long p3 = pack2(eL1.z, eL1.w);
#pragma unroll
            for (int q = 0; q < QN; q++) {
                unsigned long long acc = 0ull;
                fma2(acc, p0, wreg[q * 4 + 0]);
                fma2(acc, p1, wreg[q * 4 + 1]);
                fma2(acc, p2, wreg[q * 4 + 2]);
                fma2(acc, p3, wreg[q * 4 + 3]);
                float x, y; unpack2(acc, x, y);
                rL[q] = x + y;
            }
        }
        {
            const unsigned long long p0 = pack2(eH0.x, eH0.y);
            const unsigned long long p1 = pack2(eH0.z, eH0.w);
            const unsigned long long p2 = pack2(eH1.x, eH1.y);
            const unsigned long long p3 = pack2(eH1.z, eH1.w);
#pragma unroll
            for (int q = 0; q < QN; q++) {
                unsigned long long acc = 0ull;
                fma2(acc, p0, wreg[q * 4 + 0]);
                fma2(acc, p1, wreg[q * 4 + 1]);
                fma2(acc, p2, wreg[q * 4 + 2]);
                fma2(acc, p3, wreg[q * 4 + 3]);
                float x, y; unpack2(acc, x, y);
                rH[q] = x + y;
            }
        }

        // ---- vector reduce-scatter: lane l ends with u of value (l&15),
        //      point A on half 0, point B on half 1 ----
        float r[QN];
        // round off=16: select-free thanks to the load-time role swap
#pragma unroll
        for (int q = 0; q < QN; q++)
            r[q] = rL[q] + __shfl_xor_sync(0xffffffffu, rH[q], 16);
        // round off=8
#pragma unroll
        for (int j = 0; j < 4; j++) {
            const float keep = b3 ? r[j + 8] : r[j];
            const float send = b3 ? r[j] : r[j + 8];
            r[j] = keep + __shfl_xor_sync(0xffffffffu, send, 8);
        }
#pragma unroll
        for (int j = 4; j < 8; j++)   // partner value identical; b3=1 result dead
            r[j] = r[j] + __shfl_xor_sync(0xffffffffu, r[j], 8);
        // round off=4
#pragma unroll
        for (int j = 0; j < 4; j++) {
            const float keep = b2 ? r[j + 4] : r[j];
            const float send = b2 ? r[j] : r[j + 4];
            r[j] = keep + __shfl_xor_sync(0xffffffffu, send, 4);
        }
        // round off=2
#pragma unroll
        for (int j = 0; j < 2; j++) {
            const float keep = b1 ? r[j + 2] : r[j];
            const float send = b1 ? r[j] : r[j + 2];
            r[j] = keep + __shfl_xor_sync(0xffffffffu, send, 2);
        }
        // round off=1
        float u;
        {
            const float keep = b0 ? r[1] : r[0];
            const float send = b0 ? r[0] : r[1];
            u = keep + __shfl_xor_sync(0xffffffffu, send, 1);
        }

        // ---- spline: 24 active lanes (12 q x 2 points), divide-free ----
        float v = 0.0f;
        if (active) {
            const float uu = u + my_bi;
            const float e  = __expf(sc2 * uu);
            const float s  = __fdividef(1.0f, 1.0f + e);   // 0.5*(tanh+1)

            float s22 = s * (float)NSPANS;                 // scaled domain
            int sp = (int)s22;
            sp = sp > (NSPANS - 1) ? (NSPANS - 1) : (sp < 0 ? 0 : sp);
            const float fj = (float)sp;

            const float L1  = s22 - fj;
            const float R1  = 1.0f - L1;
            const float L2  = s22 - fmaxf(fj - 1.0f, 0.0f);
            const float R2  = fminf(fj + 2.0f, (float)NSPANS) - s22;
            const float L3  = s22 - fmaxf(fj - 2.0f, 0.0f);
            const float R3  = fminf(fj + 3.0f, (float)NSPANS) - s22;

            // scaled reciprocal knot spans (constants; edge spans differ)
            const float THIRD = 0.33333333333333333f;
            const float i2a = (sp == 0)  ? 1.0f : 0.5f;
            const float i2b = (sp == 21) ? 1.0f : 0.5f;
            const float i3a = (sp == 0)  ? 1.0f : ((sp == 1)  ? 0.5f : THIRD);
            const float i3b = (sp == 0 || sp == 21) ? 0.5f : THIRD;
            const float i3c = (sp == 20) ? 0.5f : ((sp == 21) ? 1.0f : THIRD);

            // local de Boor, all denominators folded into i* constants
            float N0 = R1, N1 = L1, N2, N3, t, sv;
            t = N0 * i2a;  N0 = R1 * t;       sv = L2 * t;
            t = N1 * i2b;  N1 = sv + R2 * t;  N2 = L1 * t;
            t = N0 * i3a;  N0 = R1 * t;       sv = L3 * t;
            t = N1 * i3b;  N1 = sv + R2 * t;  sv = L2 * t;
            t = N2 * i3c;  N2 = sv + R3 * t;  N3 = L1 * t;

            const float phi = N0 * crow[sp]     + N1 * crow[sp + 1]
                            + N2 * crow[sp + 2] + N3 * crow[sp + 3];
            v = phi * my_a;
        }

        // sum 12 q-contribs per point within each 16-lane half
#pragma unroll
        for (int off = 8; off; off >>= 1)
            v += __shfl_xor_sync(0xffffffffu, v, off);

        if (lane == 0)               out[nA] = v + bo;
        if (lane == 16 && nB < npts) out[nB] = v + bo;

        eL0 = fL0; eL1 = fL1; eH0 = fH0; eH1 = fH1;
        n = nn;
    }
}

extern "C" void kernel_launch(void* const* d_in, const int* in_sizes, int n_in,
                              void* d_out, int out_size)
{
    const float* emb         = (const float*)d_in[0];
    const float* W           = (const float*)d_in[1];
    const float* b_inner     = (const float*)d_in[2];
    const float* inner_scale = (const float*)d_in[3];
    const float* coeffs      = (const float*)d_in[4];
    const float* a_out       = (const float*)d_in[5];
    const float* b_out       = (const float*)d_in[6];
    float* out = (float*)d_out;

    const int npts = in_sizes[0] / INPUT_DIM;

    ka_bspline_kernel<<<456, 128>>>(emb, W, b_inner, inner_scale, coeffs,
                                    a_out, b_out, out, npts);
}